// round 2
// baseline (speedup 1.0000x reference)
#include <cuda_runtime.h>
#include <cuda_fp16.h>
#include <cstdint>

#define CHUNK    50000
#define AEV      384
#define HD1      160
#define HD2      128
#define HD3      96
#define TILE_M   128
#define TPS      391            // ceil(50000/128)
#define NUM_TILES (4*TPS)       // 1564
#define NTHREADS 256
#define ALPHA_F  0.1f

// strides in halves (padded for conflict-free LDS)
#define SA1 392     // A tile / W1 rows: 384 + 8
#define SH1 168     // H1 / W2 rows: 160 + 8
#define SH2 136     // H2 / W3 rows: 128 + 8

// smem layout (bytes)
#define OFF_MISC  0
#define OFF_A     2048
#define A_BYTES   (TILE_M * SA1 * 2)           // 100352
#define OFF_W     (OFF_A + A_BYTES)            // 102400
#define W_BYTES   (HD1 * SA1 * 2)              // 125440
#define SMEM_DYN  (OFF_W + W_BYTES)            // 227840

// aliases inside A region after layer 1
#define OFF_H1    OFF_A
#define H1_BYTES  (TILE_M * SH1 * 2)           // 43008
#define OFF_H2    (OFF_A + H1_BYTES)
// aliases inside W region after layer 1
#define OFF_W2    OFF_W
#define W2_BYTES  (HD2 * SH1 * 2)              // 43008
#define OFF_W3    (OFF_W + W2_BYTES)

// ---------------- device scratch ----------------
__device__ __half g_W1t[4][HD1*AEV];   // [n][k]
__device__ __half g_W2t[4][HD2*HD1];
__device__ __half g_W3t[4][HD3*HD2];
__device__ float  g_partials[NUM_TILES];

__device__ __forceinline__ float celu_f(float x) {
    return fmaxf(x, 0.f) + fminf(0.f, ALPHA_F * (__expf(x * (1.f / ALPHA_F)) - 1.f));
}

__device__ __forceinline__ void mma16816(float (&d)[4],
    uint32_t a0, uint32_t a1, uint32_t a2, uint32_t a3, uint32_t b0, uint32_t b1) {
    asm volatile(
        "mma.sync.aligned.m16n8k16.row.col.f32.f16.f16.f32 "
        "{%0,%1,%2,%3}, {%4,%5,%6,%7}, {%8,%9}, {%0,%1,%2,%3};"
        : "+f"(d[0]), "+f"(d[1]), "+f"(d[2]), "+f"(d[3])
        : "r"(a0), "r"(a1), "r"(a2), "r"(a3), "r"(b0), "r"(b1));
}

// A row-major [row][k] stride SA, B stored [n][k] stride SB (== col-major K x N).
template<int MT, int NT, int KS, int SA, int SB>
__device__ __forceinline__ void gemm(const __half* __restrict__ A,
                                     const __half* __restrict__ B,
                                     float (&acc)[MT][NT][4],
                                     int g, int t, int r0, int n0) {
#pragma unroll 2
    for (int k0 = 0; k0 < KS * 16; k0 += 16) {
        uint32_t b0[NT], b1[NT];
#pragma unroll
        for (int nt = 0; nt < NT; nt++) {
            const __half* bp = B + (n0 + nt * 8 + g) * SB + k0 + 2 * t;
            b0[nt] = *(const uint32_t*)bp;
            b1[nt] = *(const uint32_t*)(bp + 8);
        }
#pragma unroll
        for (int mt = 0; mt < MT; mt++) {
            const __half* ap = A + (r0 + mt * 16 + g) * SA + k0 + 2 * t;
            uint32_t a0 = *(const uint32_t*)ap;
            uint32_t a2 = *(const uint32_t*)(ap + 8);
            uint32_t a1 = *(const uint32_t*)(ap + 8 * SA);
            uint32_t a3 = *(const uint32_t*)(ap + 8 * SA + 8);
#pragma unroll
            for (int nt = 0; nt < NT; nt++)
                mma16816(acc[mt][nt], a0, a1, a2, a3, b0[nt], b1[nt]);
        }
    }
}

// bias + celu + fp16 store to H [row][c] stride SH
template<int MT, int NT, int SH>
__device__ __forceinline__ void epi_store(float (&acc)[MT][NT][4],
                                          const float* __restrict__ bias,
                                          __half* __restrict__ H,
                                          int g, int t, int r0, int n0) {
#pragma unroll
    for (int mt = 0; mt < MT; mt++) {
#pragma unroll
        for (int nt = 0; nt < NT; nt++) {
            int c = n0 + nt * 8 + 2 * t;
            float bc0 = bias[c], bc1 = bias[c + 1];
            int row = r0 + mt * 16 + g;
            __half2 h0 = __floats2half2_rn(celu_f(acc[mt][nt][0] + bc0),
                                           celu_f(acc[mt][nt][1] + bc1));
            __half2 h1 = __floats2half2_rn(celu_f(acc[mt][nt][2] + bc0),
                                           celu_f(acc[mt][nt][3] + bc1));
            *(__half2*)(H + row * SH + c) = h0;
            *(__half2*)(H + (row + 8) * SH + c) = h1;
        }
    }
}

// ---------------- kernel 1: weight convert + transpose --------------
__global__ void convert_weights(const float* __restrict__ W1,
                                const float* __restrict__ W2,
                                const float* __restrict__ W3) {
    int i = blockIdx.x * blockDim.x + threadIdx.x;
    constexpr int N1 = 4 * HD1 * AEV;
    constexpr int N2 = 4 * HD2 * HD1;
    constexpr int N3 = 4 * HD3 * HD2;
    if (i < N1) {
        int s = i / (HD1 * AEV), r = i % (HD1 * AEV);
        int n = r / AEV, k = r % AEV;
        g_W1t[s][r] = __float2half(W1[(s * AEV + k) * HD1 + n]);
    } else if ((i -= N1) < N2) {
        int s = i / (HD2 * HD1), r = i % (HD2 * HD1);
        int n = r / HD1, k = r % HD1;
        g_W2t[s][r] = __float2half(W2[(s * HD1 + k) * HD2 + n]);
    } else if ((i -= N2) < N3) {
        int s = i / (HD3 * HD2), r = i % (HD3 * HD2);
        int n = r / HD2, k = r % HD2;
        g_W3t[s][r] = __float2half(W3[(s * HD2 + k) * HD3 + n]);
    }
}

// ---------------- kernel 2: fused MLP per 128-atom tile -------------
__global__ void __launch_bounds__(NTHREADS, 1)
fused_mlp_kernel(const float* __restrict__ aev,
                 const float* __restrict__ b1, const float* __restrict__ b2,
                 const float* __restrict__ b3, const float* __restrict__ W4,
                 const float* __restrict__ b4,
                 const int* __restrict__ Hi, const int* __restrict__ Ci,
                 const int* __restrict__ Ni, const int* __restrict__ Oi) {
    extern __shared__ char smc[];
    const int tid = threadIdx.x;
    const int wid = tid >> 5;
    const int lid = tid & 31;
    const int g   = lid >> 2;       // 0..7
    const int t   = lid & 3;        // 0..3
    const int mgrp = wid & 1;       // 2 M groups of 64 rows
    const int ngrp = wid >> 1;      // 4 N groups
    const int r0 = 64 * mgrp;

    const int bid = blockIdx.x;
    const int s = bid / TPS;
    const int tile = bid % TPS;
    const int rowbase = tile * TILE_M;

    float* b1s = (float*)(smc + OFF_MISC);            // 160
    float* b2s = b1s + HD1;                           // 128
    float* b3s = b2s + HD2;                           // 96
    float* w4s = b3s + HD3;                           // 96
    float* wsum = w4s + HD3;                          // 8
    __half* As = (__half*)(smc + OFF_A);
    __half* Ws = (__half*)(smc + OFF_W);
    __half* H1s = (__half*)(smc + OFF_H1);
    __half* H2s = (__half*)(smc + OFF_H2);
    __half* W2s = (__half*)(smc + OFF_W2);
    __half* W3s = (__half*)(smc + OFF_W3);

    // ---- biases / W4 ----
    for (int i = tid; i < HD1; i += NTHREADS) b1s[i] = b1[s * HD1 + i];
    for (int i = tid; i < HD2; i += NTHREADS) b2s[i] = b2[s * HD2 + i];
    for (int i = tid; i < HD3; i += NTHREADS) b3s[i] = b3[s * HD3 + i];
    for (int i = tid; i < HD3; i += NTHREADS) w4s[i] = W4[s * HD3 + i];

    // ---- gather A: 128 rows x 384 f32 -> fp16 (padded row-major) ----
    const int* idxp = (s == 0) ? Hi : (s == 1) ? Ci : (s == 2) ? Ni : Oi;
    for (int gg = tid; gg < TILE_M * (AEV / 4); gg += NTHREADS) {
        int r = gg / (AEV / 4);
        int k0 = (gg % (AEV / 4)) * 4;
        uint2 val;
        int ar = rowbase + r;
        if (ar < CHUNK) {
            int a = idxp[ar];
            float4 f = *(const float4*)(aev + (size_t)a * AEV + k0);
            __half2 h01 = __floats2half2_rn(f.x, f.y);
            __half2 h23 = __floats2half2_rn(f.z, f.w);
            val.x = *(uint32_t*)&h01;
            val.y = *(uint32_t*)&h23;
        } else {
            val.x = 0u; val.y = 0u;
        }
        *(uint2*)(As + r * SA1 + k0) = val;
    }
    // ---- W1^T -> smem (160 x 384, stride 392) ----
    {
        const __half* w1 = g_W1t[s];
        for (int gg = tid; gg < HD1 * (AEV / 8); gg += NTHREADS) {
            int n = gg / (AEV / 8);
            int k0 = (gg % (AEV / 8)) * 8;
            *(uint4*)(Ws + n * SA1 + k0) = *(const uint4*)(w1 + n * AEV + k0);
        }
    }
    __syncthreads();

    // ---- layer 1: [128x384] @ [384x160] ----
    {
        float acc[4][5][4];
#pragma unroll
        for (int i = 0; i < 4; i++)
#pragma unroll
            for (int j = 0; j < 5; j++)
#pragma unroll
                for (int q = 0; q < 4; q++) acc[i][j][q] = 0.f;
        gemm<4, 5, 24, SA1, SA1>(As, Ws, acc, g, t, r0, 40 * ngrp);
        __syncthreads();   // everyone done reading A/W1 before overwrite
        epi_store<4, 5, SH1>(acc, b1s, H1s, g, t, r0, 40 * ngrp);
    }
    // ---- stage W2^T / W3^T (overwrites W1 region) ----
    {
        const __half* w2 = g_W2t[s];
        for (int gg = tid; gg < HD2 * (HD1 / 8); gg += NTHREADS) {
            int n = gg / (HD1 / 8);
            int k0 = (gg % (HD1 / 8)) * 8;
            *(uint4*)(W2s + n * SH1 + k0) = *(const uint4*)(w2 + n * HD1 + k0);
        }
        const __half* w3 = g_W3t[s];
        for (int gg = tid; gg < HD3 * (HD2 / 8); gg += NTHREADS) {
            int n = gg / (HD2 / 8);
            int k0 = (gg % (HD2 / 8)) * 8;
            *(uint4*)(W3s + n * SH2 + k0) = *(const uint4*)(w3 + n * HD2 + k0);
        }
    }
    __syncthreads();

    // ---- layer 2: [128x160] @ [160x128] ----
    {
        float acc[4][4][4];
#pragma unroll
        for (int i = 0; i < 4; i++)
#pragma unroll
            for (int j = 0; j < 4; j++)
#pragma unroll
                for (int q = 0; q < 4; q++) acc[i][j][q] = 0.f;
        gemm<4, 4, 10, SH1, SH1>(H1s, W2s, acc, g, t, r0, 32 * ngrp);
        __syncthreads();
        epi_store<4, 4, SH2>(acc, b2s, H2s, g, t, r0, 32 * ngrp);
    }
    __syncthreads();

    // ---- layer 3 + layer 4 fused ----
    {
        float acc[4][3][4];
#pragma unroll
        for (int i = 0; i < 4; i++)
#pragma unroll
            for (int j = 0; j < 3; j++)
#pragma unroll
                for (int q = 0; q < 4; q++) acc[i][j][q] = 0.f;
        gemm<4, 3, 8, SH2, SH2>(H2s, W3s, acc, g, t, r0, 24 * ngrp);

        int n0 = 24 * ngrp;
        float p = 0.f;
#pragma unroll
        for (int mt = 0; mt < 4; mt++) {
            int row0 = rowbase + r0 + mt * 16 + g;
            int row1 = row0 + 8;
#pragma unroll
            for (int nt = 0; nt < 3; nt++) {
                int c = n0 + nt * 8 + 2 * t;
                float w0 = w4s[c], w1v = w4s[c + 1];
                float bc0 = b3s[c], bc1 = b3s[c + 1];
                if (row0 < CHUNK)
                    p += celu_f(acc[mt][nt][0] + bc0) * w0
                       + celu_f(acc[mt][nt][1] + bc1) * w1v;
                if (row1 < CHUNK)
                    p += celu_f(acc[mt][nt][2] + bc0) * w0
                       + celu_f(acc[mt][nt][3] + bc1) * w1v;
            }
        }
#pragma unroll
        for (int o = 16; o > 0; o >>= 1) p += __shfl_xor_sync(0xFFFFFFFFu, p, o);
        if (lid == 0) wsum[wid] = p;
    }
    __syncthreads();
    if (tid == 0) {
        float tot = 0.f;
#pragma unroll
        for (int i = 0; i < 8; i++) tot += wsum[i];
        int vr = CHUNK - rowbase; if (vr > TILE_M) vr = TILE_M;
        tot += (float)vr * b4[s];
        g_partials[bid] = tot;
    }
}

// ---------------- kernel 3: deterministic final reduction -----------
__global__ void reduce_partials(float* __restrict__ out) {
    __shared__ float ws[16];
    int tid = threadIdx.x;
    float a = 0.f;
    for (int i = tid; i < NUM_TILES; i += 512) a += g_partials[i];
#pragma unroll
    for (int o = 16; o > 0; o >>= 1) a += __shfl_xor_sync(0xFFFFFFFFu, a, o);
    if ((tid & 31) == 0) ws[tid >> 5] = a;
    __syncthreads();
    if (tid < 16) {
        float v = ws[tid];
#pragma unroll
        for (int o = 8; o > 0; o >>= 1) v += __shfl_xor_sync(0xFFFFu, v, o);
        if (tid == 0) out[0] = v;
    }
}

// ---------------- launch ----------------
extern "C" void kernel_launch(void* const* d_in, const int* in_sizes, int n_in,
                              void* d_out, int out_size) {
    const float* aev = (const float*)d_in[0];
    const float* W1  = (const float*)d_in[1];
    const float* b1  = (const float*)d_in[2];
    const float* W2  = (const float*)d_in[3];
    const float* b2  = (const float*)d_in[4];
    const float* W3  = (const float*)d_in[5];
    const float* b3  = (const float*)d_in[6];
    const float* W4  = (const float*)d_in[7];
    const float* b4  = (const float*)d_in[8];
    const int* Hi = (const int*)d_in[9];
    const int* Ci = (const int*)d_in[10];
    const int* Ni = (const int*)d_in[11];
    const int* Oi = (const int*)d_in[12];

    cudaFuncSetAttribute(fused_mlp_kernel, cudaFuncAttributeMaxDynamicSharedMemorySize, SMEM_DYN);

    convert_weights<<<1472, 256>>>(W1, W2, W3);
    fused_mlp_kernel<<<NUM_TILES, NTHREADS, SMEM_DYN>>>(aev, b1, b2, b3, W4, b4, Hi, Ci, Ni, Oi);
    reduce_partials<<<1, 512>>>((float*)d_out);
}

// round 3
// speedup vs baseline: 1.8272x; 1.8272x over previous
#include <cuda_runtime.h>
#include <cuda_fp16.h>
#include <cstdint>

#define CHUNK    50000
#define AEV      384
#define HD1      160
#define HD2      128
#define HD3      96
#define TILE_M   128
#define TPS      391            // ceil(50000/128)
#define NUM_TILES (4*TPS)       // 1564
#define NTHREADS 256
#define ALPHA_F  0.1f

// strides in halves (padded: conflict-free for LDSM 8-row pattern)
#define SA1 392     // 784B/row -> 4-bank shift per row
#define SH1 168     // 336B/row -> 20-bank shift
#define SH2 136     // 272B/row -> 4-bank shift

// smem layout (bytes)
#define OFF_MISC  0
#define OFF_A     2048
#define A_BYTES   (TILE_M * SA1 * 2)           // 100352
#define SMEM_DYN  (OFF_A + A_BYTES)            // 102400 -> 2 CTAs/SM

// aliases inside A region after layer 1
#define OFF_H1    OFF_A
#define H1_BYTES  (TILE_M * SH1 * 2)           // 43008
#define OFF_H2    (OFF_A + H1_BYTES)           // +34816 (fits in A region)

// fragment geometry: KP = K/32 (uint4 covers 2 k-steps of 16)
#define KP1 12
#define KP2 5
#define KP3 4
#define N81 20
#define N82 16
#define N83 12

// ---------------- device scratch ----------------
__device__ uint4 g_W1f[4][N81*KP1*32];   // [n8][kp][lane] per-lane B fragments
__device__ uint4 g_W2f[4][N82*KP2*32];
__device__ uint4 g_W3f[4][N83*KP3*32];
__device__ float g_partials[NUM_TILES];

__device__ __forceinline__ float celu_f(float x) {
    return fmaxf(x, 0.f) + fminf(0.f, ALPHA_F * (__expf(x * (1.f / ALPHA_F)) - 1.f));
}

__device__ __forceinline__ void mma16816(float (&d)[4],
    uint32_t a0, uint32_t a1, uint32_t a2, uint32_t a3, uint32_t b0, uint32_t b1) {
    asm volatile(
        "mma.sync.aligned.m16n8k16.row.col.f32.f16.f16.f32 "
        "{%0,%1,%2,%3}, {%4,%5,%6,%7}, {%8,%9}, {%0,%1,%2,%3};"
        : "+f"(d[0]), "+f"(d[1]), "+f"(d[2]), "+f"(d[3])
        : "r"(a0), "r"(a1), "r"(a2), "r"(a3), "r"(b0), "r"(b1));
}

__device__ __forceinline__ void ldsm4(uint32_t (&r)[4], uint32_t addr) {
    asm volatile("ldmatrix.sync.aligned.m8n8.x4.shared.b16 {%0,%1,%2,%3}, [%4];"
        : "=r"(r[0]), "=r"(r[1]), "=r"(r[2]), "=r"(r[3]) : "r"(addr));
}

__device__ __forceinline__ uint32_t smem_u32(const void* p) {
    uint32_t a;
    asm("{ .reg .u64 t; cvta.to.shared.u64 t, %1; cvt.u32.u64 %0, t; }" : "=r"(a) : "l"(p));
    return a;
}

// A from smem via ldmatrix; B fragments straight from global (L2-resident).
// fB is pre-offset: g_WXf[s] + n8base*KP*32 + lid. Offsets in uint4 units.
template<int MT, int NT, int KP, int SA>
__device__ __forceinline__ void gemm_g(uint32_t aBase, const uint4* __restrict__ fB,
                                       float (&acc)[MT][NT][4], int lane, int r0) {
    uint32_t a0 = aBase + (uint32_t)(((r0 + (lane & 15)) * SA + ((lane >> 4) << 3)) * 2);
#pragma unroll
    for (int kp = 0; kp < KP; kp++) {
        uint4 B[NT];
#pragma unroll
        for (int nt = 0; nt < NT; nt++) B[nt] = fB[(nt * KP + kp) << 5];
#pragma unroll
        for (int mt = 0; mt < MT; mt++) {
            uint32_t ra[4], rb[4];
            uint32_t ad = a0 + (uint32_t)(mt * (16 * SA * 2) + kp * 64);
            ldsm4(ra, ad);
            ldsm4(rb, ad + 32);
#pragma unroll
            for (int nt = 0; nt < NT; nt++) {
                mma16816(acc[mt][nt], ra[0], ra[1], ra[2], ra[3], B[nt].x, B[nt].y);
                mma16816(acc[mt][nt], rb[0], rb[1], rb[2], rb[3], B[nt].z, B[nt].w);
            }
        }
    }
}

// bias + celu + fp16 store to H [row][c] stride SH
template<int MT, int NT, int SH>
__device__ __forceinline__ void epi_store(float (&acc)[MT][NT][4],
                                          const float* __restrict__ bias,
                                          __half* __restrict__ H,
                                          int g, int t, int r0, int n0) {
#pragma unroll
    for (int mt = 0; mt < MT; mt++) {
#pragma unroll
        for (int nt = 0; nt < NT; nt++) {
            int c = n0 + nt * 8 + 2 * t;
            float bc0 = bias[c], bc1 = bias[c + 1];
            int row = r0 + mt * 16 + g;
            __half2 h0 = __floats2half2_rn(celu_f(acc[mt][nt][0] + bc0),
                                           celu_f(acc[mt][nt][1] + bc1));
            __half2 h1 = __floats2half2_rn(celu_f(acc[mt][nt][2] + bc0),
                                           celu_f(acc[mt][nt][3] + bc1));
            *(__half2*)(H + row * SH + c) = h0;
            *(__half2*)(H + (row + 8) * SH + c) = h1;
        }
    }
}

// ---------------- kernel 1: weights -> per-lane fragment layout -----
__device__ __forceinline__ uint4 pack8(const float* __restrict__ W, int N, int n, int k0) {
    __half2 p;
    uint4 r;
    p = __floats2half2_rn(W[(k0 + 0) * N + n], W[(k0 + 1) * N + n]);  r.x = *(uint32_t*)&p;
    p = __floats2half2_rn(W[(k0 + 8) * N + n], W[(k0 + 9) * N + n]);  r.y = *(uint32_t*)&p;
    p = __floats2half2_rn(W[(k0 + 16) * N + n], W[(k0 + 17) * N + n]); r.z = *(uint32_t*)&p;
    p = __floats2half2_rn(W[(k0 + 24) * N + n], W[(k0 + 25) * N + n]); r.w = *(uint32_t*)&p;
    return r;
}

__global__ void convert_weights(const float* __restrict__ W1,
                                const float* __restrict__ W2,
                                const float* __restrict__ W3) {
    const int E1 = N81 * KP1 * 32, E2 = N82 * KP2 * 32, E3 = N83 * KP3 * 32;
    const int PS = E1 + E2 + E3;
    int i = blockIdx.x * blockDim.x + threadIdx.x;
    if (i >= 4 * PS) return;
    int s = i / PS, e = i % PS;
    if (e < E1) {
        int n8 = e / (KP1 * 32), rem = e % (KP1 * 32), kp = rem >> 5, lane = rem & 31;
        int n = n8 * 8 + (lane >> 2), k0 = kp * 32 + 2 * (lane & 3);
        g_W1f[s][e] = pack8(W1 + s * AEV * HD1, HD1, n, k0);
    } else if ((e -= E1) < E2) {
        int n8 = e / (KP2 * 32), rem = e % (KP2 * 32), kp = rem >> 5, lane = rem & 31;
        int n = n8 * 8 + (lane >> 2), k0 = kp * 32 + 2 * (lane & 3);
        g_W2f[s][e] = pack8(W2 + s * HD1 * HD2, HD2, n, k0);
    } else {
        e -= E2;
        int n8 = e / (KP3 * 32), rem = e % (KP3 * 32), kp = rem >> 5, lane = rem & 31;
        int n = n8 * 8 + (lane >> 2), k0 = kp * 32 + 2 * (lane & 3);
        g_W3f[s][e] = pack8(W3 + s * HD2 * HD3, HD3, n, k0);
    }
}

// ---------------- kernel 2: fused MLP per 128-atom tile -------------
__global__ void __launch_bounds__(NTHREADS, 2)
fused_mlp_kernel(const float* __restrict__ aev,
                 const float* __restrict__ b1, const float* __restrict__ b2,
                 const float* __restrict__ b3, const float* __restrict__ W4,
                 const float* __restrict__ b4,
                 const int* __restrict__ Hi, const int* __restrict__ Ci,
                 const int* __restrict__ Ni, const int* __restrict__ Oi) {
    extern __shared__ char smc[];
    const int tid = threadIdx.x;
    const int wid = tid >> 5;
    const int lid = tid & 31;
    const int g   = lid >> 2;
    const int t   = lid & 3;
    const int mgrp = wid & 1;       // 2 M groups of 64 rows
    const int ngrp = wid >> 1;      // 4 N groups
    const int r0 = 64 * mgrp;

    const int bid = blockIdx.x;
    const int s = bid / TPS;
    const int tile = bid % TPS;
    const int rowbase = tile * TILE_M;

    float* b1s = (float*)(smc + OFF_MISC);            // 160
    float* b2s = b1s + HD1;                           // 128
    float* b3s = b2s + HD2;                           // 96
    float* w4s = b3s + HD3;                           // 96
    float* wsum = w4s + HD3;                          // 8
    __half* As  = (__half*)(smc + OFF_A);
    __half* H1s = (__half*)(smc + OFF_H1);
    __half* H2s = (__half*)(smc + OFF_H2);
    const uint32_t aU  = smem_u32(As);
    const uint32_t h1U = smem_u32(H1s);
    const uint32_t h2U = smem_u32(H2s);

    // per-warp fragment pointers (global, L2-resident)
    const uint4* f1 = g_W1f[s] + (5 * ngrp) * (KP1 * 32) + lid;
    const uint4* f2 = g_W2f[s] + (4 * ngrp) * (KP2 * 32) + lid;
    const uint4* f3 = g_W3f[s] + (3 * ngrp) * (KP3 * 32) + lid;

    // ---- biases / W4 ----
    for (int i = tid; i < HD1; i += NTHREADS) b1s[i] = b1[s * HD1 + i];
    for (int i = tid; i < HD2; i += NTHREADS) b2s[i] = b2[s * HD2 + i];
    for (int i = tid; i < HD3; i += NTHREADS) b3s[i] = b3[s * HD3 + i];
    for (int i = tid; i < HD3; i += NTHREADS) w4s[i] = W4[s * HD3 + i];

    // ---- gather A: 128 rows x 384 f32 -> fp16 (padded row-major) ----
    const int* idxp = (s == 0) ? Hi : (s == 1) ? Ci : (s == 2) ? Ni : Oi;
    for (int gg = tid; gg < TILE_M * (AEV / 4); gg += NTHREADS) {
        int r = gg / (AEV / 4);
        int k0 = (gg % (AEV / 4)) * 4;
        uint2 val;
        int ar = rowbase + r;
        if (ar < CHUNK) {
            int a = idxp[ar];
            float4 f = *(const float4*)(aev + (size_t)a * AEV + k0);
            __half2 h01 = __floats2half2_rn(f.x, f.y);
            __half2 h23 = __floats2half2_rn(f.z, f.w);
            val.x = *(uint32_t*)&h01;
            val.y = *(uint32_t*)&h23;
        } else {
            val.x = 0u; val.y = 0u;
        }
        *(uint2*)(As + r * SA1 + k0) = val;
    }
    __syncthreads();

    // ---- layer 1: [128x384] @ [384x160] ----
    {
        float acc[4][5][4];
#pragma unroll
        for (int i = 0; i < 4; i++)
#pragma unroll
            for (int j = 0; j < 5; j++)
#pragma unroll
                for (int q = 0; q < 4; q++) acc[i][j][q] = 0.f;
        gemm_g<4, 5, KP1, SA1>(aU, f1, acc, lid, r0);
        __syncthreads();   // all warps done reading A before H1 overwrites it
        epi_store<4, 5, SH1>(acc, b1s, H1s, g, t, r0, 40 * ngrp);
    }
    __syncthreads();

    // ---- layer 2: [128x160] @ [160x128] ----
    {
        float acc[4][4][4];
#pragma unroll
        for (int i = 0; i < 4; i++)
#pragma unroll
            for (int j = 0; j < 4; j++)
#pragma unroll
                for (int q = 0; q < 4; q++) acc[i][j][q] = 0.f;
        gemm_g<4, 4, KP2, SH1>(h1U, f2, acc, lid, r0);
        epi_store<4, 4, SH2>(acc, b2s, H2s, g, t, r0, 32 * ngrp);   // H2 disjoint from H1
    }
    __syncthreads();

    // ---- layer 3 + layer 4 fused ----
    {
        float acc[4][3][4];
#pragma unroll
        for (int i = 0; i < 4; i++)
#pragma unroll
            for (int j = 0; j < 3; j++)
#pragma unroll
                for (int q = 0; q < 4; q++) acc[i][j][q] = 0.f;
        gemm_g<4, 3, KP3, SH2>(h2U, f3, acc, lid, r0);

        int n0 = 24 * ngrp;
        float p = 0.f;
#pragma unroll
        for (int mt = 0; mt < 4; mt++) {
            int row0 = rowbase + r0 + mt * 16 + g;
            int row1 = row0 + 8;
#pragma unroll
            for (int nt = 0; nt < 3; nt++) {
                int c = n0 + nt * 8 + 2 * t;
                float w0 = w4s[c], w1v = w4s[c + 1];
                float bc0 = b3s[c], bc1 = b3s[c + 1];
                if (row0 < CHUNK)
                    p += celu_f(acc[mt][nt][0] + bc0) * w0
                       + celu_f(acc[mt][nt][1] + bc1) * w1v;
                if (row1 < CHUNK)
                    p += celu_f(acc[mt][nt][2] + bc0) * w0
                       + celu_f(acc[mt][nt][3] + bc1) * w1v;
            }
        }
#pragma unroll
        for (int o = 16; o > 0; o >>= 1) p += __shfl_xor_sync(0xFFFFFFFFu, p, o);
        if (lid == 0) wsum[wid] = p;
    }
    __syncthreads();
    if (tid == 0) {
        float tot = 0.f;
#pragma unroll
        for (int i = 0; i < 8; i++) tot += wsum[i];
        int vr = CHUNK - rowbase; if (vr > TILE_M) vr = TILE_M;
        tot += (float)vr * b4[s];
        g_partials[bid] = tot;
    }
}

// ---------------- kernel 3: deterministic final reduction -----------
__global__ void reduce_partials(float* __restrict__ out) {
    __shared__ float ws[16];
    int tid = threadIdx.x;
    float a = 0.f;
    for (int i = tid; i < NUM_TILES; i += 512) a += g_partials[i];
#pragma unroll
    for (int o = 16; o > 0; o >>= 1) a += __shfl_xor_sync(0xFFFFFFFFu, a, o);
    if ((tid & 31) == 0) ws[tid >> 5] = a;
    __syncthreads();
    if (tid < 16) {
        float v = ws[tid];
#pragma unroll
        for (int o = 8; o > 0; o >>= 1) v += __shfl_xor_sync(0xFFFFu, v, o);
        if (tid == 0) out[0] = v;
    }
}

// ---------------- launch ----------------
extern "C" void kernel_launch(void* const* d_in, const int* in_sizes, int n_in,
                              void* d_out, int out_size) {
    const float* aev = (const float*)d_in[0];
    const float* W1  = (const float*)d_in[1];
    const float* b1  = (const float*)d_in[2];
    const float* W2  = (const float*)d_in[3];
    const float* b2  = (const float*)d_in[4];
    const float* W3  = (const float*)d_in[5];
    const float* b3  = (const float*)d_in[6];
    const float* W4  = (const float*)d_in[7];
    const float* b4  = (const float*)d_in[8];
    const int* Hi = (const int*)d_in[9];
    const int* Ci = (const int*)d_in[10];
    const int* Ni = (const int*)d_in[11];
    const int* Oi = (const int*)d_in[12];

    cudaFuncSetAttribute(fused_mlp_kernel, cudaFuncAttributeMaxDynamicSharedMemorySize, SMEM_DYN);

    convert_weights<<<184, 256>>>(W1, W2, W3);
    fused_mlp_kernel<<<NUM_TILES, NTHREADS, SMEM_DYN>>>(aev, b1, b2, b3, W4, b4, Hi, Ci, Ni, Oi);
    reduce_partials<<<1, 512>>>((float*)d_out);
}